// round 11
// baseline (speedup 1.0000x reference)
#include <cuda_runtime.h>

// PostProcessingBlock: 50 NOTEARS-style iterations, 512 independent 64x64
// matrices, one 256-thread CTA per matrix, 3 CTAs/SM.
// 8 matmuls/iter: poly m^63 = ((m^15)^2)^2 @ m^3 reuses the trace chain's
// m^15/m^3; trace(m^30) = dot(m^15, m^15^T). mm64: f32x2 FMA, 4x4 tile.
// This round: alpha in registers (one fewer barrier), unroll-8 mainloop,
// pointer-walked operand addressing.

#define LDM   68
#define MATF  (64 * LDM)
#define NTH   256

typedef unsigned long long u64;

__device__ __forceinline__ u64 rep2(float v) {
    u64 r;
    asm("mov.b64 %0, {%1, %1};" : "=l"(r) : "r"(__float_as_uint(v)));
    return r;
}
__device__ __forceinline__ void ffma2(u64& d, u64 a, u64 b) {
    asm("fma.rn.f32x2 %0, %1, %2, %0;" : "+l"(d) : "l"(a), "l"(b));
}

// C = A @ B, 64x64x64 fp32 in smem, 256 threads, 4x4 tile per thread.
// Caller guarantees C distinct from A and B (A == B allowed).
__device__ __forceinline__ void mm64(float* __restrict__ C,
                                     const float* __restrict__ A,
                                     const float* __restrict__ B,
                                     int tx, int ty)
{
    u64 acc[4][2];
#pragma unroll
    for (int r = 0; r < 4; r++) { acc[r][0] = 0ULL; acc[r][1] = 0ULL; }

    const float* a0p = A + (ty + 0) * LDM;
    const float* a1p = A + (ty + 1) * LDM;
    const float* a2p = A + (ty + 2) * LDM;
    const float* a3p = A + (ty + 3) * LDM;
    const float* bp  = B + tx;

#pragma unroll 8
    for (int k0 = 0; k0 < 64; k0 += 4) {
        float a0[4], a1[4], a2[4], a3[4];
        *reinterpret_cast<float4*>(a0) = *reinterpret_cast<const float4*>(a0p); a0p += 4;
        *reinterpret_cast<float4*>(a1) = *reinterpret_cast<const float4*>(a1p); a1p += 4;
        *reinterpret_cast<float4*>(a2) = *reinterpret_cast<const float4*>(a2p); a2p += 4;
        *reinterpret_cast<float4*>(a3) = *reinterpret_cast<const float4*>(a3p); a3p += 4;

#pragma unroll
        for (int ki = 0; ki < 4; ki++) {
            const ulonglong2 b = *reinterpret_cast<const ulonglong2*>(bp);
            bp += LDM;
            ffma2(acc[0][0], rep2(a0[ki]), b.x);
            ffma2(acc[0][1], rep2(a0[ki]), b.y);
            ffma2(acc[1][0], rep2(a1[ki]), b.x);
            ffma2(acc[1][1], rep2(a1[ki]), b.y);
            ffma2(acc[2][0], rep2(a2[ki]), b.x);
            ffma2(acc[2][1], rep2(a2[ki]), b.y);
            ffma2(acc[3][0], rep2(a3[ki]), b.x);
            ffma2(acc[3][1], rep2(a3[ki]), b.y);
        }
    }

#pragma unroll
    for (int r = 0; r < 4; r++)
        *reinterpret_cast<ulonglong2*>(C + (ty + r) * LDM + tx) =
            make_ulonglong2(acc[r][0], acc[r][1]);
}

__global__ __launch_bounds__(NTH, 3)
void ppb_kernel(const float* __restrict__ adj, float* __restrict__ out)
{
    extern __shared__ float sm[];
    float* xs = sm;                 // current x
    float* w0 = xs + MATF;          // rotating work buffers
    float* w1 = w0 + MATF;
    float* w2 = w1 + MATF;
    float* red = w2 + MATF;         // [0..7] warp partials

    const int tid = threadIdx.x;
    const int tx = (tid & 15) * 4;
    const int ty = (tid >> 4) * 4;
    const int bidx = blockIdx.x;
    const float4* Ain4 = reinterpret_cast<const float4*>(adj + (size_t)bidx * 4096);

    // Load adj -> xs; scores = threshold(adj,0.5) kept in 16 registers.
    float scf[16];
#pragma unroll
    for (int s = 0; s < 4; s++) {
        const int e4 = tid + s * NTH;
        const float4 v = Ain4[e4];
        const int i = e4 >> 4, j = (e4 & 15) * 4;
        float* xp = xs + i * LDM + j;
        xp[0] = v.x; xp[1] = v.y; xp[2] = v.z; xp[3] = v.w;
        scf[s * 4 + 0] = (v.x > 0.5f) ? v.x : 0.0f;
        scf[s * 4 + 1] = (v.y > 0.5f) ? v.y : 0.0f;
        scf[s * 4 + 2] = (v.z > 0.5f) ? v.z : 0.0f;
        scf[s * 4 + 3] = (v.w > 0.5f) ? v.w : 0.0f;
    }
    __syncthreads();

    const float INV64  = 1.0f / 64.0f;
    const float SHRINK = 0.002f * 0.01f;

    // alpha lives in a register, updated identically by every thread.
    float alpha = 0.0f;

    // Invariant at loop top (iter >= 1): pA = m^15(x), pB = m^3(x), pC free.
    float* pA = w0;
    float* pB = w1;
    float* pC = w2;

#pragma unroll 1
    for (int it = 0; it < 50; it++) {
        const bool need_poly = (alpha != 0.0f);   // iter 0 only

        if (need_poly) {
            // m^63 = ((m^15)^2)^2 @ m^3 — destinations distinct from sources.
            mm64(pC, pA, pA, tx, ty);  __syncthreads();  // m^30 -> pC (m^15 dead)
            mm64(pA, pC, pC, tx, ty);  __syncthreads();  // m^60 -> pA
            mm64(pC, pA, pB, tx, ty);  __syncthreads();  // m^63 -> pC (m^30 dead)
        }

        // x update (reads pC^T) fused with build of m = I + x*x/64 into pA.
        const float a2s = 2.0f * alpha * INV64;
#pragma unroll
        for (int s = 0; s < 4; s++) {
            const int e4 = tid + s * NTH;
            const int i = e4 >> 4, j = (e4 & 15) * 4;
            float* xp = xs + i * LDM + j;
            float* mp = pA + i * LDM + j;
#pragma unroll
            for (int c = 0; c < 4; c++) {
                float x = xp[c];
                float g = -scf[s * 4 + c];
                if (need_poly)
                    g += (a2s * x) * pC[(j + c) * LDM + i];
                const float til = x - 0.01f * g;
                float nx = fabsf(til) - SHRINK;
                nx = fmaxf(nx, 0.0f);
                x = 1.0f - fmaxf(1.0f - nx, 0.0f);
                xp[c] = x;
                mp[c] = x * x * INV64 + ((i == j + c) ? 1.0f : 0.0f);
            }
        }
        __syncthreads();

        // trace chain: m (pA) -> m^2, m^3, m^6, m^12, m^15; keep m^15 & m^3.
        mm64(pB, pA, pA, tx, ty);  __syncthreads();  // m^2  -> pB (old m^3 dead)
        mm64(pC, pB, pA, tx, ty);  __syncthreads();  // m^3  -> pC (m^63 dead)
        mm64(pB, pC, pC, tx, ty);  __syncthreads();  // m^6  -> pB (m^2 dead)
        mm64(pA, pB, pB, tx, ty);  __syncthreads();  // m^12 -> pA (m dead)
        mm64(pB, pA, pC, tx, ty);  __syncthreads();  // m^15 -> pB (m^6 dead)

        // h = trace(m^30)/64 - 1 ; trace(m^30) = dot(m^15, m^15^T)
        float part = 0.0f;
#pragma unroll
        for (int s = 0; s < 16; s++) {
            const int e = tid + s * NTH;
            const int i = e >> 6, k = e & 63;
            part += pB[i * LDM + k] * pB[k * LDM + i];
        }
#pragma unroll
        for (int off = 16; off > 0; off >>= 1)
            part += __shfl_xor_sync(0xFFFFFFFFu, part, off);
        if ((tid & 31) == 0) red[tid >> 5] = part;
        __syncthreads();

        // Every thread redundantly sums the 8 partials (identical order ->
        // identical alpha in all threads); no second barrier needed because
        // red is next written only after 8 matmuls' worth of barriers.
        float t = 0.0f;
#pragma unroll
        for (int w = 0; w < 8; w++) t += red[w];
        alpha += 0.01f * (t * INV64 - 1.0f);

        // rotate: m^15 in pB, m^3 in pC, pA free.
        float* tmp = pA;
        pA = pB;      // m^15
        pB = pC;      // m^3
        pC = tmp;     // free
    }

    // output = threshold(x, 0.5)
    float4* Out4 = reinterpret_cast<float4*>(out + (size_t)bidx * 4096);
#pragma unroll
    for (int s = 0; s < 4; s++) {
        const int e4 = tid + s * NTH;
        const int i = e4 >> 4, j = (e4 & 15) * 4;
        const float* xp = xs + i * LDM + j;
        float4 v;
        v.x = (xp[0] > 0.5f) ? xp[0] : 0.0f;
        v.y = (xp[1] > 0.5f) ? xp[1] : 0.0f;
        v.z = (xp[2] > 0.5f) ? xp[2] : 0.0f;
        v.w = (xp[3] > 0.5f) ? xp[3] : 0.0f;
        Out4[e4] = v;
    }
}

extern "C" void kernel_launch(void* const* d_in, const int* in_sizes, int n_in,
                              void* d_out, int out_size)
{
    const float* adj = (const float*)d_in[0];
    float* out = (float*)d_out;

    const int batches = in_sizes[0] >> 12;
    const size_t smem = (size_t)(4 * MATF + 8) * sizeof(float);

    cudaFuncSetAttribute(ppb_kernel, cudaFuncAttributeMaxDynamicSharedMemorySize, (int)smem);
    ppb_kernel<<<batches, NTH, smem>>>(adj, out);
}

// round 14
// speedup vs baseline: 2.5103x; 2.5103x over previous
#include <cuda_runtime.h>
#include <cstdint>

// PostProcessingBlock: 50 NOTEARS-style iterations on 512 independent 64x64
// matrices. One 256-thread CTA per matrix, 3 CTAs/SM.
// Matmuls on the tensor pipe via baseline PTX mma.sync m16n8k8 tf32
// (sm_80+ ISA -> compiles for plain sm_103; tcgen05 is 'a'-target-only and
// unavailable in this build). 8 mm/iter: poly m63 = ((m15)^2)^2 @ m3 reuses
// the trace chain's m15/m3; trace(m30) = dot(m15, m15^T).
// Each matrix product is kept in N-form ([M,K] row-major, LDM=68) and, when
// needed as a right operand, T-form (transpose). 4 rotating smem slots.

typedef uint32_t u32;

#define LDM  68
#define SLOT (64 * LDM)
#define NTH  256

__device__ __forceinline__ float tf32r(float x) {
    u32 q;
    asm("cvt.rna.tf32.f32 %0, %1;" : "=r"(q) : "f"(x));
    return __uint_as_float(q);
}

__device__ __forceinline__ void mma8(float d[4],
                                     u32 a0, u32 a1, u32 a2, u32 a3,
                                     u32 b0, u32 b1)
{
    asm volatile(
        "mma.sync.aligned.m16n8k8.row.col.f32.tf32.tf32.f32 "
        "{%0,%1,%2,%3}, {%4,%5,%6,%7}, {%8,%9}, {%0,%1,%2,%3};"
        : "+f"(d[0]), "+f"(d[1]), "+f"(d[2]), "+f"(d[3])
        : "r"(a0), "r"(a1), "r"(a2), "r"(a3), "r"(b0), "r"(b1));
}

// D = A @ B where An = A in N-form, Bt = B in T-form (i.e. B^T row-major).
// Stores D to Dn (N-form) and, if ST, to Dt (T-form), tf32-rounded.
// In-place reuse of input slots is safe: stores are barrier-separated from
// all operand reads. Ends with __syncthreads().
template <bool ST>
__device__ __forceinline__ void mm_step(const float* An, const float* Bt,
                                        float* Dn, float* Dt,
                                        int m0, int n0, int gid, int tig)
{
    float d[4][4];
#pragma unroll
    for (int t = 0; t < 4; t++)
#pragma unroll
        for (int c = 0; c < 4; c++) d[t][c] = 0.0f;

    const float* ap0 = An + (m0 + gid) * LDM + tig;       // rows m0+gid, m0+gid+8
    const float* ap1 = ap0 + 8 * LDM;
    const float* bp  = Bt + (n0 + gid) * LDM + tig;       // T-form rows n0+8t+gid

#pragma unroll
    for (int k0 = 0; k0 < 64; k0 += 8) {
        const u32 a0 = __float_as_uint(ap0[k0]);
        const u32 a1 = __float_as_uint(ap1[k0]);
        const u32 a2 = __float_as_uint(ap0[k0 + 4]);
        const u32 a3 = __float_as_uint(ap1[k0 + 4]);
#pragma unroll
        for (int t = 0; t < 4; t++) {
            const u32 b0 = __float_as_uint(bp[t * 8 * LDM + k0]);
            const u32 b1 = __float_as_uint(bp[t * 8 * LDM + k0 + 4]);
            mma8(d[t], a0, a1, a2, a3, b0, b1);
        }
    }

    __syncthreads();   // all operand reads complete before any store

    const int r0 = m0 + gid, r1 = r0 + 8;
#pragma unroll
    for (int t = 0; t < 4; t++) {
        const int col = n0 + 8 * t + 2 * tig;
        const float q0 = tf32r(d[t][0]);
        const float q1 = tf32r(d[t][1]);
        const float q2 = tf32r(d[t][2]);
        const float q3 = tf32r(d[t][3]);
        *reinterpret_cast<float2*>(Dn + r0 * LDM + col) = make_float2(q0, q1);
        *reinterpret_cast<float2*>(Dn + r1 * LDM + col) = make_float2(q2, q3);
        if (ST) {
            Dt[(col    ) * LDM + r0] = q0;
            Dt[(col + 1) * LDM + r0] = q1;
            Dt[(col    ) * LDM + r1] = q2;
            Dt[(col + 1) * LDM + r1] = q3;
        }
    }
    __syncthreads();
}

__global__ __launch_bounds__(NTH, 3)
void ppb_kernel(const float* __restrict__ adj, float* __restrict__ out)
{
    extern __shared__ float sm[];
    // 4 rotating slots + 8-float reduction area
    float* pNa = sm;                 // role at loop top: m15 N-form
    float* pTa = sm + SLOT;          // m15 T-form
    float* pT3 = sm + 2 * SLOT;      // m3 T-form
    float* pF  = sm + 3 * SLOT;      // free
    float* red = sm + 4 * SLOT;

    const int tid  = threadIdx.x;
    const int lane = tid & 31;
    const int gid  = lane >> 2;        // 0..7
    const int tig  = lane & 3;         // 0..3
    const int wrp  = tid >> 5;         // 0..7
    const int m0   = (wrp & 3) * 16;   // warp output rows
    const int n0   = (wrp >> 2) * 32;  // warp output cols

    // per-thread 4x4 tile for x / scores / elementwise ops
    const int j0 = (tid & 15) * 4;
    const int i0 = (tid >> 4) * 4;
    const float* A0 = adj + (size_t)blockIdx.x * 4096;

    float xr[16], scf[16];
#pragma unroll
    for (int r = 0; r < 4; r++) {
        const float4 v = *reinterpret_cast<const float4*>(A0 + (i0 + r) * 64 + j0);
        xr[r*4+0] = v.x; xr[r*4+1] = v.y; xr[r*4+2] = v.z; xr[r*4+3] = v.w;
        scf[r*4+0] = (v.x > 0.5f) ? v.x : 0.0f;
        scf[r*4+1] = (v.y > 0.5f) ? v.y : 0.0f;
        scf[r*4+2] = (v.z > 0.5f) ? v.z : 0.0f;
        scf[r*4+3] = (v.w > 0.5f) ? v.w : 0.0f;
    }

    const float INV64  = 1.0f / 64.0f;
    const float SHRINK = 0.002f * 0.01f;
    float alpha = 0.0f;

#pragma unroll 1
    for (int it = 0; it < 50; it++) {
        const bool np = (it > 0);
        const bool bm = (it < 49);

        if (np) {
            // m30 = m15 @ m15 (N+T, in-place over m15 pair)
            mm_step<true >(pNa, pTa, pNa, pTa, m0, n0, gid, tig);
            // m60 = m30 @ m30 (N only -> pF)
            mm_step<false>(pNa, pTa, pF, 0, m0, n0, gid, tig);
            // m63 = m60 @ m3 (N only -> pNa)
            mm_step<false>(pF, pT3, pNa, 0, m0, n0, gid, tig);
        }

        // x update (reads m63 N-form transposed) + build m = I + x*x/64
        // into pTa (N-form) and pT3 (T-form), tf32-rounded.
        const float a2s = 2.0f * alpha * INV64;
        float mv[4][4];   // mv[r][c] = m[i0+r][j0+c]
#pragma unroll
        for (int c = 0; c < 4; c++) {
            float4 pv = make_float4(0.f, 0.f, 0.f, 0.f);
            if (np)
                pv = *reinterpret_cast<const float4*>(pNa + (j0 + c) * LDM + i0);
            const float pvv[4] = { pv.x, pv.y, pv.z, pv.w };
#pragma unroll
            for (int r = 0; r < 4; r++) {
                float x = xr[r*4+c];
                const float g = -scf[r*4+c] + (a2s * x) * pvv[r];
                const float til = x - 0.01f * g;
                float nx = fmaxf(fabsf(til) - SHRINK, 0.0f);
                x = 1.0f - fmaxf(1.0f - nx, 0.0f);
                xr[r*4+c] = x;
                mv[r][c] = tf32r(x * x * INV64 + ((i0 + r == j0 + c) ? 1.0f : 0.0f));
            }
        }

        if (bm) {
#pragma unroll
            for (int r = 0; r < 4; r++)
                *reinterpret_cast<float4*>(pTa + (i0 + r) * LDM + j0) =
                    make_float4(mv[r][0], mv[r][1], mv[r][2], mv[r][3]);
#pragma unroll
            for (int c = 0; c < 4; c++)
                *reinterpret_cast<float4*>(pT3 + (j0 + c) * LDM + i0) =
                    make_float4(mv[0][c], mv[1][c], mv[2][c], mv[3][c]);
            __syncthreads();

            // trace chain: m (pTa/pT3) -> m2, m3, m6, m12, m15
            mm_step<false>(pTa, pT3, pF, 0, m0, n0, gid, tig);            // m2  N->pF
            mm_step<true >(pF, pT3, pTa, pT3, m0, n0, gid, tig);          // m3  N->pTa T->pT3
            mm_step<true >(pTa, pT3, pF, pNa, m0, n0, gid, tig);          // m6  N->pF  T->pNa
            mm_step<false>(pF, pNa, pTa, 0, m0, n0, gid, tig);            // m12 N->pTa
            mm_step<true >(pTa, pT3, pNa, pF, m0, n0, gid, tig);          // m15 N->pNa T->pF

            // h = trace(m^30)/64 - 1 ; trace(m^30) = dot(m15, m15^T)
            float part = 0.0f;
#pragma unroll
            for (int s = 0; s < 16; s++) {
                const int e = tid + s * NTH;
                const int i = e >> 6, k = e & 63;
                part += pNa[i * LDM + k] * pNa[k * LDM + i];
            }
#pragma unroll
            for (int off = 16; off > 0; off >>= 1)
                part += __shfl_xor_sync(0xFFFFFFFFu, part, off);
            if (lane == 0) red[wrp] = part;
            __syncthreads();
            float t = 0.0f;
#pragma unroll
            for (int w = 0; w < 8; w++) t += red[w];
            alpha += 0.01f * (t * INV64 - 1.0f);
            __syncthreads();

            // rotate roles: m15T ended in pF, free slot is old pTa.
            float* tmp = pTa; pTa = pF; pF = tmp;
        }
    }

    // output = threshold(x, 0.5)
    float* O0 = out + (size_t)blockIdx.x * 4096;
#pragma unroll
    for (int r = 0; r < 4; r++) {
        float4 v;
        v.x = (xr[r*4+0] > 0.5f) ? xr[r*4+0] : 0.0f;
        v.y = (xr[r*4+1] > 0.5f) ? xr[r*4+1] : 0.0f;
        v.z = (xr[r*4+2] > 0.5f) ? xr[r*4+2] : 0.0f;
        v.w = (xr[r*4+3] > 0.5f) ? xr[r*4+3] : 0.0f;
        *reinterpret_cast<float4*>(O0 + (i0 + r) * 64 + j0) = v;
    }
}

extern "C" void kernel_launch(void* const* d_in, const int* in_sizes, int n_in,
                              void* d_out, int out_size)
{
    const float* adj = (const float*)d_in[0];
    float* out = (float*)d_out;

    const int batches = in_sizes[0] >> 12;
    const size_t smem = (size_t)(4 * SLOT + 8) * sizeof(float);

    cudaFuncSetAttribute(ppb_kernel, cudaFuncAttributeMaxDynamicSharedMemorySize, (int)smem);
    ppb_kernel<<<batches, NTH, smem>>>(adj, out);
}

// round 15
// speedup vs baseline: 2.9146x; 1.1611x over previous
#include <cuda_runtime.h>
#include <cstdint>

// PostProcessingBlock: 50 NOTEARS-style iterations on 512 independent 64x64
// matrices. One 128-thread CTA per matrix, 4 CTAs/SM (3 smem slots, 52.3KB).
// Matmuls via PTX mma.sync m16n8k8 tf32 (sm_80+ baseline ISA; tcgen05 is
// 'a'-target-only and unavailable in this build). 4 warps, 32x32 tile each.
// 8 mm/iter: poly m63 = ((m15)^2)^2 @ m3 reuses the trace chain's m15/m3;
// trace(m30) = dot(m15, m15^T). Products kept in N-form ([M,K] row-major,
// LDM=68) and T-form (transpose) as needed; slot schedule is in-place with
// all stores barrier-separated from operand reads.

typedef uint32_t u32;

#define LDM  68
#define SLOT (64 * LDM)
#define NTH  128

__device__ __forceinline__ float tf32r(float x) {
    u32 q;
    asm("cvt.rna.tf32.f32 %0, %1;" : "=r"(q) : "f"(x));
    return __uint_as_float(q);
}

__device__ __forceinline__ void mma8(float d[4],
                                     u32 a0, u32 a1, u32 a2, u32 a3,
                                     u32 b0, u32 b1)
{
    asm volatile(
        "mma.sync.aligned.m16n8k8.row.col.f32.tf32.tf32.f32 "
        "{%0,%1,%2,%3}, {%4,%5,%6,%7}, {%8,%9}, {%0,%1,%2,%3};"
        : "+f"(d[0]), "+f"(d[1]), "+f"(d[2]), "+f"(d[3])
        : "r"(a0), "r"(a1), "r"(a2), "r"(a3), "r"(b0), "r"(b1));
}

// D = A @ B with An = A N-form, Bt = B T-form (B^T row-major).
// Warp computes a 32x32 tile. Stores D N-form to Dn and, if ST, T-form to Dt.
// In-place slot reuse is safe: a barrier separates all reads from stores.
// Ends with __syncthreads().
template <bool ST>
__device__ __forceinline__ void mm_step(const float* An, const float* Bt,
                                        float* Dn, float* Dt,
                                        int m0, int n0, int gid, int tig)
{
    float d[2][4][4];
#pragma unroll
    for (int mt = 0; mt < 2; mt++)
#pragma unroll
        for (int nt = 0; nt < 4; nt++)
#pragma unroll
            for (int c = 0; c < 4; c++) d[mt][nt][c] = 0.0f;

    const float* ab = An + (m0 + gid) * LDM + tig;
    const float* bb = Bt + (n0 + gid) * LDM + tig;

#pragma unroll
    for (int k0 = 0; k0 < 64; k0 += 8) {
        u32 a[2][4];
#pragma unroll
        for (int mt = 0; mt < 2; mt++) {
            a[mt][0] = __float_as_uint(ab[(16*mt    ) * LDM + k0]);
            a[mt][1] = __float_as_uint(ab[(16*mt + 8) * LDM + k0]);
            a[mt][2] = __float_as_uint(ab[(16*mt    ) * LDM + k0 + 4]);
            a[mt][3] = __float_as_uint(ab[(16*mt + 8) * LDM + k0 + 4]);
        }
#pragma unroll
        for (int nt = 0; nt < 4; nt++) {
            const u32 b0 = __float_as_uint(bb[(8*nt) * LDM + k0]);
            const u32 b1 = __float_as_uint(bb[(8*nt) * LDM + k0 + 4]);
            mma8(d[0][nt], a[0][0], a[0][1], a[0][2], a[0][3], b0, b1);
            mma8(d[1][nt], a[1][0], a[1][1], a[1][2], a[1][3], b0, b1);
        }
    }

    __syncthreads();   // all operand reads complete before any store

#pragma unroll
    for (int mt = 0; mt < 2; mt++) {
        const int r0 = m0 + 16*mt + gid, r1 = r0 + 8;
#pragma unroll
        for (int nt = 0; nt < 4; nt++) {
            const int col = n0 + 8*nt + 2*tig;
            const float q0 = tf32r(d[mt][nt][0]);
            const float q1 = tf32r(d[mt][nt][1]);
            const float q2 = tf32r(d[mt][nt][2]);
            const float q3 = tf32r(d[mt][nt][3]);
            *reinterpret_cast<float2*>(Dn + r0 * LDM + col) = make_float2(q0, q1);
            *reinterpret_cast<float2*>(Dn + r1 * LDM + col) = make_float2(q2, q3);
            if (ST) {
                Dt[(col    ) * LDM + r0] = q0;
                Dt[(col + 1) * LDM + r0] = q1;
                Dt[(col    ) * LDM + r1] = q2;
                Dt[(col + 1) * LDM + r1] = q3;
            }
        }
    }
    __syncthreads();
}

__global__ __launch_bounds__(NTH, 4)
void ppb_kernel(const float* __restrict__ adj, float* __restrict__ out)
{
    extern __shared__ float sm[];
    float* sA = sm;                  // loop-top role: m15 N-form
    float* sB = sm + SLOT;           // m15 T-form
    float* sC = sm + 2 * SLOT;       // m3 T-form
    float* red = sm + 3 * SLOT;      // [0..3] warp partials

    const int tid  = threadIdx.x;
    const int lane = tid & 31;
    const int gid  = lane >> 2;       // 0..7
    const int tig  = lane & 3;        // 0..3
    const int wrp  = tid >> 5;        // 0..3
    const int m0   = (wrp & 1) * 32;  // warp rows
    const int n0   = (wrp >> 1) * 32; // warp cols

    // per-thread elementwise tile: rows i0..i0+7, cols j0..j0+3
    const int j0 = (tid & 15) * 4;
    const int i0 = (tid >> 4) * 8;
    const float* A0 = adj + (size_t)blockIdx.x * 4096;

    float xr[32];
#pragma unroll
    for (int r = 0; r < 8; r++) {
        const float4 v = *reinterpret_cast<const float4*>(A0 + (i0 + r) * 64 + j0);
        xr[r*4+0] = v.x; xr[r*4+1] = v.y; xr[r*4+2] = v.z; xr[r*4+3] = v.w;
    }

    const float INV64  = 1.0f / 64.0f;
    const float SHRINK = 0.002f * 0.01f;
    float alpha = 0.0f;

#pragma unroll 1
    for (int it = 0; it < 50; it++) {
        const bool np = (it > 0);
        const bool bm = (it < 49);

        if (np) {
            // invariant: sA=m15N, sB=m15T, sC=m3T
            mm_step<true >(sA, sB, sA, sB, m0, n0, gid, tig);   // m30: N->A, T->B
            mm_step<false>(sA, sB, sA, sA, m0, n0, gid, tig);   // m60: N->A
            mm_step<true >(sA, sC, sA, sB, m0, n0, gid, tig);   // m63: T->B (N discard->A)
        }

        // x update (reads m63T @ sB row-wise) + build m = I + x*x/64
        // (scores recomputed from L2-resident adj; N->sA, T->sC)
        const float a2s = 2.0f * alpha * INV64;
#pragma unroll
        for (int r = 0; r < 8; r++) {
            const int i = i0 + r;
            const float4 av = *reinterpret_cast<const float4*>(A0 + i * 64 + j0);
            float4 pv = make_float4(0.f, 0.f, 0.f, 0.f);
            if (np)
                pv = *reinterpret_cast<const float4*>(sB + i * LDM + j0);
            const float sc[4] = { (av.x > 0.5f) ? av.x : 0.0f,
                                  (av.y > 0.5f) ? av.y : 0.0f,
                                  (av.z > 0.5f) ? av.z : 0.0f,
                                  (av.w > 0.5f) ? av.w : 0.0f };
            const float pvv[4] = { pv.x, pv.y, pv.z, pv.w };
            float m4[4];
#pragma unroll
            for (int c = 0; c < 4; c++) {
                float x = xr[r*4+c];
                const float g = -sc[c] + (a2s * x) * pvv[c];
                const float til = x - 0.01f * g;
                float nx = fmaxf(fabsf(til) - SHRINK, 0.0f);
                x = 1.0f - fmaxf(1.0f - nx, 0.0f);
                xr[r*4+c] = x;
                m4[c] = tf32r(x * x * INV64 + ((i == j0 + c) ? 1.0f : 0.0f));
            }
            if (bm) {
                *reinterpret_cast<float4*>(sA + i * LDM + j0) =
                    make_float4(m4[0], m4[1], m4[2], m4[3]);
                sC[(j0+0) * LDM + i] = m4[0];
                sC[(j0+1) * LDM + i] = m4[1];
                sC[(j0+2) * LDM + i] = m4[2];
                sC[(j0+3) * LDM + i] = m4[3];
            }
        }

        if (bm) {
            __syncthreads();
            // trace chain: m in sA (N) / sC (T)
            mm_step<false>(sA, sC, sB, sB, m0, n0, gid, tig);   // m2:  N->B
            mm_step<true >(sB, sC, sB, sC, m0, n0, gid, tig);   // m3:  N->B, T->C (in-place)
            mm_step<true >(sB, sC, sA, sB, m0, n0, gid, tig);   // m6:  N->A, T->B
            mm_step<false>(sA, sB, sA, sA, m0, n0, gid, tig);   // m12: N->A (in-place)
            mm_step<true >(sA, sC, sA, sB, m0, n0, gid, tig);   // m15: N->A, T->B

            // h = trace(m^30)/64 - 1 ; trace(m^30) = dot(m15, m15^T) on sA
            float part = 0.0f;
#pragma unroll
            for (int s = 0; s < 32; s++) {
                const int e = tid + s * NTH;
                const int i = e >> 6, k = e & 63;
                part += sA[i * LDM + k] * sA[k * LDM + i];
            }
#pragma unroll
            for (int off = 16; off > 0; off >>= 1)
                part += __shfl_xor_sync(0xFFFFFFFFu, part, off);
            if (lane == 0) red[wrp] = part;
            __syncthreads();
            const float t = (red[0] + red[1]) + (red[2] + red[3]);
            alpha += 0.01f * (t * INV64 - 1.0f);
            __syncthreads();
        }
    }

    // output = threshold(x, 0.5)
    float* O0 = out + (size_t)blockIdx.x * 4096;
#pragma unroll
    for (int r = 0; r < 8; r++) {
        float4 v;
        v.x = (xr[r*4+0] > 0.5f) ? xr[r*4+0] : 0.0f;
        v.y = (xr[r*4+1] > 0.5f) ? xr[r*4+1] : 0.0f;
        v.z = (xr[r*4+2] > 0.5f) ? xr[r*4+2] : 0.0f;
        v.w = (xr[r*4+3] > 0.5f) ? xr[r*4+3] : 0.0f;
        *reinterpret_cast<float4*>(O0 + (i0 + r) * 64 + j0) = v;
    }
}

extern "C" void kernel_launch(void* const* d_in, const int* in_sizes, int n_in,
                              void* d_out, int out_size)
{
    const float* adj = (const float*)d_in[0];
    float* out = (float*)d_out;

    const int batches = in_sizes[0] >> 12;
    const size_t smem = (size_t)(3 * SLOT + 8) * sizeof(float);

    cudaFuncSetAttribute(ppb_kernel, cudaFuncAttributeMaxDynamicSharedMemorySize, (int)smem);
    ppb_kernel<<<batches, NTH, smem>>>(adj, out);
}

// round 16
// speedup vs baseline: 4.7128x; 1.6169x over previous
#include <cuda_runtime.h>
#include <cuda_bf16.h>
#include <cstdint>

// PostProcessingBlock: 50 NOTEARS-style iterations on 512 independent 64x64
// matrices. One 128-thread CTA per matrix, 5 CTAs/SM (3 bf16 smem slots,
// 27.7KB). Matmuls via PTX mma.sync m16n8k16 bf16 (f32 accumulate).
// 4 warps, 32x32 tile each. 8 mm/iter: poly m63 = ((m15)^2)^2 @ m3 reuses
// the trace chain's m15/m3; trace(m30) = dot(m15, m15^T).
// Products kept in N-form ([M,K] row-major bf16, LDMB=72) and T-form
// (transpose) as needed; slot schedule identical to the passing tf32 R15.

typedef uint32_t u32;
typedef uint16_t u16;

#define LDMB 72
#define SLOT (64 * LDMB)          // bf16 elements per slot (9216 B)
#define NTH  128

__device__ __forceinline__ u32 packbf2(float lo, float hi) {
    u32 r;  // d<15:0> = cvt(b=lo), d<31:16> = cvt(a=hi)
    asm("cvt.rn.bf16x2.f32 %0, %1, %2;" : "=r"(r) : "f"(hi), "f"(lo));
    return r;
}
__device__ __forceinline__ float2 unpackbf2(u32 p) {
    const __nv_bfloat162 b = *reinterpret_cast<const __nv_bfloat162*>(&p);
    return __bfloat1622float2(b);
}
__device__ __forceinline__ float bf2f(u16 b) {
    const __nv_bfloat16 v = *reinterpret_cast<const __nv_bfloat16*>(&b);
    return __bfloat162float(v);
}

__device__ __forceinline__ void mma16(float d[4], const u32 a[4], u32 b0, u32 b1)
{
    asm volatile(
        "mma.sync.aligned.m16n8k16.row.col.f32.bf16.bf16.f32 "
        "{%0,%1,%2,%3}, {%4,%5,%6,%7}, {%8,%9}, {%0,%1,%2,%3};"
        : "+f"(d[0]), "+f"(d[1]), "+f"(d[2]), "+f"(d[3])
        : "r"(a[0]), "r"(a[1]), "r"(a[2]), "r"(a[3]), "r"(b0), "r"(b1));
}

// D = A @ B with An = A N-form, Bt = B T-form (B^T row-major), bf16.
// Warp computes a 32x32 tile (2x4 m16n8k16 frags). Stores D (bf16-rounded)
// N-form to Dn and, if ST, T-form to Dt. In-place slot reuse is safe: a
// barrier separates all reads from stores. Ends with __syncthreads().
template <bool ST>
__device__ __forceinline__ void mm_step(const u16* An, const u16* Bt,
                                        u16* Dn, u16* Dt,
                                        int m0, int n0, int gid, int tig)
{
    float d[2][4][4];
#pragma unroll
    for (int mt = 0; mt < 2; mt++)
#pragma unroll
        for (int nt = 0; nt < 4; nt++)
#pragma unroll
            for (int c = 0; c < 4; c++) d[mt][nt][c] = 0.0f;

    const u16* ab = An + (m0 + gid) * LDMB + 2 * tig;
    const u16* bb = Bt + (n0 + gid) * LDMB + 2 * tig;

#pragma unroll
    for (int k0 = 0; k0 < 64; k0 += 16) {
        u32 a[2][4];
#pragma unroll
        for (int mt = 0; mt < 2; mt++) {
            a[mt][0] = *reinterpret_cast<const u32*>(ab + (16*mt    ) * LDMB + k0);
            a[mt][1] = *reinterpret_cast<const u32*>(ab + (16*mt + 8) * LDMB + k0);
            a[mt][2] = *reinterpret_cast<const u32*>(ab + (16*mt    ) * LDMB + k0 + 8);
            a[mt][3] = *reinterpret_cast<const u32*>(ab + (16*mt + 8) * LDMB + k0 + 8);
        }
#pragma unroll
        for (int nt = 0; nt < 4; nt++) {
            const u32 b0 = *reinterpret_cast<const u32*>(bb + (8*nt) * LDMB + k0);
            const u32 b1 = *reinterpret_cast<const u32*>(bb + (8*nt) * LDMB + k0 + 8);
            mma16(d[0][nt], a[0], b0, b1);
            mma16(d[1][nt], a[1], b0, b1);
        }
    }

    __syncthreads();   // all operand reads complete before any store

#pragma unroll
    for (int mt = 0; mt < 2; mt++) {
        const int r0 = m0 + 16*mt + gid, r1 = r0 + 8;
#pragma unroll
        for (int nt = 0; nt < 4; nt++) {
            const int col = n0 + 8*nt + 2*tig;
            const u32 p01 = packbf2(d[mt][nt][0], d[mt][nt][1]);   // row r0
            const u32 p23 = packbf2(d[mt][nt][2], d[mt][nt][3]);   // row r1
            *reinterpret_cast<u32*>(Dn + r0 * LDMB + col) = p01;
            *reinterpret_cast<u32*>(Dn + r1 * LDMB + col) = p23;
            if (ST) {
                Dt[(col    ) * LDMB + r0] = (u16)(p01 & 0xFFFFu);
                Dt[(col + 1) * LDMB + r0] = (u16)(p01 >> 16);
                Dt[(col    ) * LDMB + r1] = (u16)(p23 & 0xFFFFu);
                Dt[(col + 1) * LDMB + r1] = (u16)(p23 >> 16);
            }
        }
    }
    __syncthreads();
}

__global__ __launch_bounds__(NTH, 5)
void ppb_kernel(const float* __restrict__ adj, float* __restrict__ out)
{
    extern __shared__ u16 sm[];
    u16* sA = sm;                    // loop-top role: m15 N-form
    u16* sB = sm + SLOT;             // m15 T-form
    u16* sC = sm + 2 * SLOT;         // m3 T-form
    float* red = reinterpret_cast<float*>(sm + 3 * SLOT);  // [0..3] warp partials

    const int tid  = threadIdx.x;
    const int lane = tid & 31;
    const int gid  = lane >> 2;       // 0..7
    const int tig  = lane & 3;        // 0..3
    const int wrp  = tid >> 5;        // 0..3
    const int m0   = (wrp & 1) * 32;
    const int n0   = (wrp >> 1) * 32;

    // per-thread elementwise tile: rows i0..i0+7, cols j0..j0+3
    const int j0 = (tid & 15) * 4;
    const int i0 = (tid >> 4) * 8;
    const float* A0 = adj + (size_t)blockIdx.x * 4096;

    float xr[32];
#pragma unroll
    for (int r = 0; r < 8; r++) {
        const float4 v = *reinterpret_cast<const float4*>(A0 + (i0 + r) * 64 + j0);
        xr[r*4+0] = v.x; xr[r*4+1] = v.y; xr[r*4+2] = v.z; xr[r*4+3] = v.w;
    }

    const float INV64  = 1.0f / 64.0f;
    const float SHRINK = 0.002f * 0.01f;
    float alpha = 0.0f;

#pragma unroll 1
    for (int it = 0; it < 50; it++) {
        const bool np = (it > 0);
        const bool bm = (it < 49);

        if (np) {
            // invariant: sA=m15N, sB=m15T, sC=m3T
            mm_step<true >(sA, sB, sA, sB, m0, n0, gid, tig);   // m30: N->A, T->B
            mm_step<false>(sA, sB, sA, sA, m0, n0, gid, tig);   // m60: N->A
            mm_step<true >(sA, sC, sA, sB, m0, n0, gid, tig);   // m63: T->B (N discard)
        }

        // x update (reads m63T @ sB) + build m = I + x*x/64 (N->sA, T->sC)
        const float a2s = 2.0f * alpha * INV64;
#pragma unroll
        for (int r = 0; r < 8; r++) {
            const int i = i0 + r;
            const float4 av = *reinterpret_cast<const float4*>(A0 + i * 64 + j0);
            float pvv[4] = {0.f, 0.f, 0.f, 0.f};
            if (np) {
                const uint2 praw = *reinterpret_cast<const uint2*>(sB + i * LDMB + j0);
                const float2 p0 = unpackbf2(praw.x);
                const float2 p1 = unpackbf2(praw.y);
                pvv[0] = p0.x; pvv[1] = p0.y; pvv[2] = p1.x; pvv[3] = p1.y;
            }
            const float sc[4] = { (av.x > 0.5f) ? av.x : 0.0f,
                                  (av.y > 0.5f) ? av.y : 0.0f,
                                  (av.z > 0.5f) ? av.z : 0.0f,
                                  (av.w > 0.5f) ? av.w : 0.0f };
            float m4[4];
#pragma unroll
            for (int c = 0; c < 4; c++) {
                float x = xr[r*4+c];
                const float g = -sc[c] + (a2s * x) * pvv[c];
                const float til = x - 0.01f * g;
                float nx = fmaxf(fabsf(til) - SHRINK, 0.0f);
                x = 1.0f - fmaxf(1.0f - nx, 0.0f);
                xr[r*4+c] = x;
                m4[c] = x * x * INV64 + ((i == j0 + c) ? 1.0f : 0.0f);
            }
            if (bm) {
                uint2 nw;
                nw.x = packbf2(m4[0], m4[1]);
                nw.y = packbf2(m4[2], m4[3]);
                *reinterpret_cast<uint2*>(sA + i * LDMB + j0) = nw;
                sC[(j0+0) * LDMB + i] = (u16)(nw.x & 0xFFFFu);
                sC[(j0+1) * LDMB + i] = (u16)(nw.x >> 16);
                sC[(j0+2) * LDMB + i] = (u16)(nw.y & 0xFFFFu);
                sC[(j0+3) * LDMB + i] = (u16)(nw.y >> 16);
            }
        }

        if (bm) {
            __syncthreads();
            // trace chain: m in sA (N) / sC (T)
            mm_step<false>(sA, sC, sB, sB, m0, n0, gid, tig);   // m2:  N->B
            mm_step<true >(sB, sC, sB, sC, m0, n0, gid, tig);   // m3:  N->B, T->C
            mm_step<true >(sB, sC, sA, sB, m0, n0, gid, tig);   // m6:  N->A, T->B
            mm_step<false>(sA, sB, sA, sA, m0, n0, gid, tig);   // m12: N->A
            mm_step<true >(sA, sC, sA, sB, m0, n0, gid, tig);   // m15: N->A, T->B

            // h = trace(m^30)/64 - 1 ; trace(m^30) = dot(m15, m15^T) on sA
            float part = 0.0f;
#pragma unroll
            for (int s = 0; s < 32; s++) {
                const int e = tid + s * NTH;
                const int i = e >> 6, k = e & 63;
                part += bf2f(sA[i * LDMB + k]) * bf2f(sA[k * LDMB + i]);
            }
#pragma unroll
            for (int off = 16; off > 0; off >>= 1)
                part += __shfl_xor_sync(0xFFFFFFFFu, part, off);
            if (lane == 0) red[wrp] = part;
            __syncthreads();
            const float t = (red[0] + red[1]) + (red[2] + red[3]);
            alpha += 0.01f * (t * INV64 - 1.0f);
            __syncthreads();
        }
    }

    // output = threshold(x, 0.5)
    float* O0 = out + (size_t)blockIdx.x * 4096;
#pragma unroll
    for (int r = 0; r < 8; r++) {
        float4 v;
        v.x = (xr[r*4+0] > 0.5f) ? xr[r*4+0] : 0.0f;
        v.y = (xr[r*4+1] > 0.5f) ? xr[r*4+1] : 0.0f;
        v.z = (xr[r*4+2] > 0.5f) ? xr[r*4+2] : 0.0f;
        v.w = (xr[r*4+3] > 0.5f) ? xr[r*4+3] : 0.0f;
        *reinterpret_cast<float4*>(O0 + (i0 + r) * 64 + j0) = v;
    }
}

extern "C" void kernel_launch(void* const* d_in, const int* in_sizes, int n_in,
                              void* d_out, int out_size)
{
    const float* adj = (const float*)d_in[0];
    float* out = (float*)d_out;

    const int batches = in_sizes[0] >> 12;
    const size_t smem = (size_t)(3 * SLOT) * sizeof(u16) + 32;

    cudaFuncSetAttribute(ppb_kernel, cudaFuncAttributeMaxDynamicSharedMemorySize, (int)smem);
    ppb_kernel<<<batches, NTH, smem>>>(adj, out);
}

// round 17
// speedup vs baseline: 4.7182x; 1.0012x over previous
#include <cuda_runtime.h>
#include <cuda_bf16.h>
#include <cstdint>

// PostProcessingBlock: 50 NOTEARS-style iterations on 512 independent 64x64
// matrices. One 128-thread CTA per matrix, 5 CTAs/SM (3 bf16 smem slots,
// 27.7KB). Matmuls via PTX mma.sync m16n8k16 bf16 (f32 accumulate).
// 4 warps, 32x32 tile each. 8 mm/iter: poly m63 = ((m15)^2)^2 @ m3 reuses
// the trace chain's m15/m3; trace(m30) = dot(m15, m15^T).
// Products kept in N-form ([M,K] row-major bf16, LDMB=72) and T-form
// (transpose) as needed; slot schedule identical to the passing tf32 R15.

typedef uint32_t u32;
typedef uint16_t u16;

#define LDMB 72
#define SLOT (64 * LDMB)          // bf16 elements per slot (9216 B)
#define NTH  128

__device__ __forceinline__ u32 packbf2(float lo, float hi) {
    u32 r;  // d<15:0> = cvt(b=lo), d<31:16> = cvt(a=hi)
    asm("cvt.rn.bf16x2.f32 %0, %1, %2;" : "=r"(r) : "f"(hi), "f"(lo));
    return r;
}
__device__ __forceinline__ float2 unpackbf2(u32 p) {
    const __nv_bfloat162 b = *reinterpret_cast<const __nv_bfloat162*>(&p);
    return __bfloat1622float2(b);
}
__device__ __forceinline__ float bf2f(u16 b) {
    const __nv_bfloat16 v = *reinterpret_cast<const __nv_bfloat16*>(&b);
    return __bfloat162float(v);
}

__device__ __forceinline__ void mma16(float d[4], const u32 a[4], u32 b0, u32 b1)
{
    asm volatile(
        "mma.sync.aligned.m16n8k16.row.col.f32.bf16.bf16.f32 "
        "{%0,%1,%2,%3}, {%4,%5,%6,%7}, {%8,%9}, {%0,%1,%2,%3};"
        : "+f"(d[0]), "+f"(d[1]), "+f"(d[2]), "+f"(d[3])
        : "r"(a[0]), "r"(a[1]), "r"(a[2]), "r"(a[3]), "r"(b0), "r"(b1));
}

// D = A @ B with An = A N-form, Bt = B T-form (B^T row-major), bf16.
// Warp computes a 32x32 tile (2x4 m16n8k16 frags). Stores D (bf16-rounded)
// N-form to Dn and, if ST, T-form to Dt. In-place slot reuse is safe: a
// barrier separates all reads from stores. Ends with __syncthreads().
template <bool ST>
__device__ __forceinline__ void mm_step(const u16* An, const u16* Bt,
                                        u16* Dn, u16* Dt,
                                        int m0, int n0, int gid, int tig)
{
    float d[2][4][4];
#pragma unroll
    for (int mt = 0; mt < 2; mt++)
#pragma unroll
        for (int nt = 0; nt < 4; nt++)
#pragma unroll
            for (int c = 0; c < 4; c++) d[mt][nt][c] = 0.0f;

    const u16* ab = An + (m0 + gid) * LDMB + 2 * tig;
    const u16* bb = Bt + (n0 + gid) * LDMB + 2 * tig;

#pragma unroll
    for (int k0 = 0; k0 < 64; k0 += 16) {
        u32 a[2][4];
#pragma unroll
        for (int mt = 0; mt < 2; mt++) {
            a[mt][0] = *reinterpret_cast<const u32*>(ab + (16*mt    ) * LDMB + k0);
            a[mt][1] = *reinterpret_cast<const u32*>(ab + (16*mt + 8) * LDMB + k0);
            a[mt][2] = *reinterpret_cast<const u32*>(ab + (16*mt    ) * LDMB + k0 + 8);
            a[mt][3] = *reinterpret_cast<const u32*>(ab + (16*mt + 8) * LDMB + k0 + 8);
        }
#pragma unroll
        for (int nt = 0; nt < 4; nt++) {
            const u32 b0 = *reinterpret_cast<const u32*>(bb + (8*nt) * LDMB + k0);
            const u32 b1 = *reinterpret_cast<const u32*>(bb + (8*nt) * LDMB + k0 + 8);
            mma16(d[0][nt], a[0], b0, b1);
            mma16(d[1][nt], a[1], b0, b1);
        }
    }

    __syncthreads();   // all operand reads complete before any store

#pragma unroll
    for (int mt = 0; mt < 2; mt++) {
        const int r0 = m0 + 16*mt + gid, r1 = r0 + 8;
#pragma unroll
        for (int nt = 0; nt < 4; nt++) {
            const int col = n0 + 8*nt + 2*tig;
            const u32 p01 = packbf2(d[mt][nt][0], d[mt][nt][1]);   // row r0
            const u32 p23 = packbf2(d[mt][nt][2], d[mt][nt][3]);   // row r1
            *reinterpret_cast<u32*>(Dn + r0 * LDMB + col) = p01;
            *reinterpret_cast<u32*>(Dn + r1 * LDMB + col) = p23;
            if (ST) {
                Dt[(col    ) * LDMB + r0] = (u16)(p01 & 0xFFFFu);
                Dt[(col + 1) * LDMB + r0] = (u16)(p01 >> 16);
                Dt[(col    ) * LDMB + r1] = (u16)(p23 & 0xFFFFu);
                Dt[(col + 1) * LDMB + r1] = (u16)(p23 >> 16);
            }
        }
    }
    __syncthreads();
}

__global__ __launch_bounds__(NTH, 5)
void ppb_kernel(const float* __restrict__ adj, float* __restrict__ out)
{
    extern __shared__ u16 sm[];
    u16* sA = sm;                    // loop-top role: m15 N-form
    u16* sB = sm + SLOT;             // m15 T-form
    u16* sC = sm + 2 * SLOT;         // m3 T-form
    float* red = reinterpret_cast<float*>(sm + 3 * SLOT);  // [0..3] warp partials

    const int tid  = threadIdx.x;
    const int lane = tid & 31;
    const int gid  = lane >> 2;       // 0..7
    const int tig  = lane & 3;        // 0..3
    const int wrp  = tid >> 5;        // 0..3
    const int m0   = (wrp & 1) * 32;
    const int n0   = (wrp >> 1) * 32;

    // per-thread elementwise tile: rows i0..i0+7, cols j0..j0+3
    const int j0 = (tid & 15) * 4;
    const int i0 = (tid >> 4) * 8;
    const float* A0 = adj + (size_t)blockIdx.x * 4096;

    float xr[32];
#pragma unroll
    for (int r = 0; r < 8; r++) {
        const float4 v = *reinterpret_cast<const float4*>(A0 + (i0 + r) * 64 + j0);
        xr[r*4+0] = v.x; xr[r*4+1] = v.y; xr[r*4+2] = v.z; xr[r*4+3] = v.w;
    }

    const float INV64  = 1.0f / 64.0f;
    const float SHRINK = 0.002f * 0.01f;
    float alpha = 0.0f;

#pragma unroll 1
    for (int it = 0; it < 50; it++) {
        const bool np = (it > 0);
        const bool bm = (it < 49);

        if (np) {
            // invariant: sA=m15N, sB=m15T, sC=m3T
            mm_step<true >(sA, sB, sA, sB, m0, n0, gid, tig);   // m30: N->A, T->B
            mm_step<false>(sA, sB, sA, sA, m0, n0, gid, tig);   // m60: N->A
            mm_step<true >(sA, sC, sA, sB, m0, n0, gid, tig);   // m63: T->B (N discard)
        }

        // x update (reads m63T @ sB) + build m = I + x*x/64 (N->sA, T->sC)
        const float a2s = 2.0f * alpha * INV64;
#pragma unroll
        for (int r = 0; r < 8; r++) {
            const int i = i0 + r;
            const float4 av = *reinterpret_cast<const float4*>(A0 + i * 64 + j0);
            float pvv[4] = {0.f, 0.f, 0.f, 0.f};
            if (np) {
                const uint2 praw = *reinterpret_cast<const uint2*>(sB + i * LDMB + j0);
                const float2 p0 = unpackbf2(praw.x);
                const float2 p1 = unpackbf2(praw.y);
                pvv[0] = p0.x; pvv[1] = p0.y; pvv[2] = p1.x; pvv[3] = p1.y;
            }
            const float sc[4] = { (av.x > 0.5f) ? av.x : 0.0f,
                                  (av.y > 0.5f) ? av.y : 0.0f,
                                  (av.z > 0.5f) ? av.z : 0.0f,
                                  (av.w > 0.5f) ? av.w : 0.0f };
            float m4[4];
#pragma unroll
            for (int c = 0; c < 4; c++) {
                float x = xr[r*4+c];
                const float g = -sc[c] + (a2s * x) * pvv[c];
                const float til = x - 0.01f * g;
                float nx = fmaxf(fabsf(til) - SHRINK, 0.0f);
                x = 1.0f - fmaxf(1.0f - nx, 0.0f);
                xr[r*4+c] = x;
                m4[c] = x * x * INV64 + ((i == j0 + c) ? 1.0f : 0.0f);
            }
            if (bm) {
                uint2 nw;
                nw.x = packbf2(m4[0], m4[1]);
                nw.y = packbf2(m4[2], m4[3]);
                *reinterpret_cast<uint2*>(sA + i * LDMB + j0) = nw;
                sC[(j0+0) * LDMB + i] = (u16)(nw.x & 0xFFFFu);
                sC[(j0+1) * LDMB + i] = (u16)(nw.x >> 16);
                sC[(j0+2) * LDMB + i] = (u16)(nw.y & 0xFFFFu);
                sC[(j0+3) * LDMB + i] = (u16)(nw.y >> 16);
            }
        }

        if (bm) {
            __syncthreads();
            // trace chain: m in sA (N) / sC (T)
            mm_step<false>(sA, sC, sB, sB, m0, n0, gid, tig);   // m2:  N->B
            mm_step<true >(sB, sC, sB, sC, m0, n0, gid, tig);   // m3:  N->B, T->C
            mm_step<true >(sB, sC, sA, sB, m0, n0, gid, tig);   // m6:  N->A, T->B
            mm_step<false>(sA, sB, sA, sA, m0, n0, gid, tig);   // m12: N->A
            mm_step<true >(sA, sC, sA, sB, m0, n0, gid, tig);   // m15: N->A, T->B

            // h = trace(m^30)/64 - 1 ; trace(m^30) = dot(m15, m15^T) on sA
            float part = 0.0f;
#pragma unroll
            for (int s = 0; s < 32; s++) {
                const int e = tid + s * NTH;
                const int i = e >> 6, k = e & 63;
                part += bf2f(sA[i * LDMB + k]) * bf2f(sA[k * LDMB + i]);
            }
#pragma unroll
            for (int off = 16; off > 0; off >>= 1)
                part += __shfl_xor_sync(0xFFFFFFFFu, part, off);
            if (lane == 0) red[wrp] = part;
            __syncthreads();
            const float t = (red[0] + red[1]) + (red[2] + red[3]);
            alpha += 0.01f * (t * INV64 - 1.0f);
            __syncthreads();
        }
    }

    // output = threshold(x, 0.5)
    float* O0 = out + (size_t)blockIdx.x * 4096;
#pragma unroll
    for (int r = 0; r < 8; r++) {
        float4 v;
        v.x = (xr[r*4+0] > 0.5f) ? xr[r*4+0] : 0.0f;
        v.y = (xr[r*4+1] > 0.5f) ? xr[r*4+1] : 0.0f;
        v.z = (xr[r*4+2] > 0.5f) ? xr[r*4+2] : 0.0f;
        v.w = (xr[r*4+3] > 0.5f) ? xr[r*4+3] : 0.0f;
        *reinterpret_cast<float4*>(O0 + (i0 + r) * 64 + j0) = v;
    }
}

extern "C" void kernel_launch(void* const* d_in, const int* in_sizes, int n_in,
                              void* d_out, int out_size)
{
    const float* adj = (const float*)d_in[0];
    float* out = (float*)d_out;

    const int batches = in_sizes[0] >> 12;
    const size_t smem = (size_t)(3 * SLOT) * sizeof(u16) + 32;

    cudaFuncSetAttribute(ppb_kernel, cudaFuncAttributeMaxDynamicSharedMemorySize, (int)smem);
    ppb_kernel<<<batches, NTH, smem>>>(adj, out);
}